// round 10
// baseline (speedup 1.0000x reference)
#include <cuda_runtime.h>
#include <math.h>

#define Bn 32
#define Rr 13
#define Cc 13
#define Aa 5
#define Kk 20
#define CELL 25
#define Nn 845                       // R*C*A
#define TOTAL (Bn * Nn)              // 27040
#define THRESH 0.5f
#define NMS_TH 0.4f

#define BPB 4                        // blocks per batch
#define CPB 212                      // cells per sub-block (last gets 209)
#define TPB 256
#define NBLK (Bn * BPB)              // 128
#define NBK (Bn * Kk)                // 640
#define CAPS 64                      // candidate capacity per (b,k)

// Static device scratch (no allocations allowed).
__device__ float  g_cs[NBK * CAPS];  // candidate scores
__device__ short  g_cn[NBK * CAPS];  // candidate box index n
__device__ float4 g_cb[NBK * CAPS];  // candidate boxes (x1,y1,x2,y2)
__device__ int    g_cnt[NBK];        // per-(b,k) counts (reset by batch tail)
__device__ int    g_bdone[Bn];       // per-batch done counters (reset by tail)

__device__ __forceinline__ float sigmoid_(float v) {
    return 1.0f / (1.0f + __expf(-v));
}

__global__ void __launch_bounds__(TPB)
region_fused(const float* __restrict__ x,
             const float* __restrict__ bias,
             float* __restrict__ out) {
    const int tid  = threadIdx.x;
    const int b    = blockIdx.x / BPB;          // batch
    const int sub  = blockIdx.x % BPB;          // sub-block within batch
    const int cellBase = sub * CPB;
    const int cells    = min(CPB, Nn - cellBase);   // 212 or 209
    const int nf       = cells * CELL;              // floats in this slice

    __shared__ float s_data[CPB * CELL];        // 21.2 KB
    __shared__ int   s_done;

    const size_t gbase = ((size_t)b * Nn + cellBase) * CELL;

    // ---- Coalesced load of this slice into shared.
    {
        const float* src = x + gbase;
        for (int i = tid; i < nf; i += TPB) s_data[i] = src[i];
    }
    __syncthreads();

    // ---- Decode + inline softmax, in place in shared.
    if (tid < cells) {
        float* t = s_data + tid * CELL;
        const int n    = cellBase + tid;
        const int a    = n % Aa;
        const int cell = n / Aa;
        const int col  = cell % Cc;
        const int row  = cell / Cc;

        float bx  = (sigmoid_(t[0]) + (float)col) * (1.0f / (float)Cc);
        float by  = (sigmoid_(t[1]) + (float)row) * (1.0f / (float)Rr);
        float bw  = __expf(t[2]) * __ldg(&bias[2 * a])     * (1.0f / (float)Rr);
        float bh  = __expf(t[3]) * __ldg(&bias[2 * a + 1]) * (1.0f / (float)Cc);
        float obj = sigmoid_(t[4]);

        t[0] = bx; t[1] = by; t[2] = bw; t[3] = bh; t[4] = obj;

        if (obj > THRESH) {
            float e[Kk];
            float s = 0.0f;
            #pragma unroll
            for (int j = 0; j < Kk; j++) { e[j] = __expf(t[5 + j]); s += e[j]; }
            float inv = 1.0f / s;

            float x1 = bx - 0.5f * bw;
            float y1 = by - 0.5f * bh;
            float4 box = make_float4(x1, y1, x1 + bw, y1 + bh);

            #pragma unroll
            for (int j = 0; j < Kk; j++) {
                float p = obj * e[j] * inv;
                if (p > THRESH) {
                    t[5 + j] = p;
                    int slot = b * Kk + j;
                    int q = atomicAdd(&g_cnt[slot], 1);
                    if (q < CAPS) {
                        g_cs[slot * CAPS + q] = p;
                        g_cn[slot * CAPS + q] = (short)n;
                        g_cb[slot * CAPS + q] = box;
                    }
                } else {
                    t[5 + j] = 0.0f;
                }
            }
        } else {
            #pragma unroll
            for (int j = 0; j < Kk; j++) t[5 + j] = 0.0f;
        }
    }
    __syncthreads();

    // ---- Coalesced store of the slice.
    {
        float* dst = out + gbase;
        for (int i = tid; i < nf; i += TPB) dst[i] = s_data[i];
    }

    // ---- Per-batch done counter: 4th arriver runs this batch's NMS tail.
    __threadfence();
    __syncthreads();
    if (tid == 0) s_done = atomicAdd(&g_bdone[b], 1);
    __syncthreads();
    if (s_done != BPB - 1) return;

    if (tid == 0) g_bdone[b] = 0;    // reset for next graph replay

    // ---- NMS for this batch's 20 class slots (threads 0..19).
    if (tid < Kk) {
        const int k    = tid;
        const int slot = b * Kk + k;
        int V = g_cnt[slot];
        g_cnt[slot] = 0;             // reset for next replay
        if (V > CAPS) V = CAPS;
        if (V > 1) {
            const float*  cs = g_cs + (size_t)slot * CAPS;
            const short*  cn = g_cn + (size_t)slot * CAPS;
            const float4* cb = g_cb + (size_t)slot * CAPS;

            unsigned sup[2] = {0u, 0u}, used[2] = {0u, 0u};

            // Greedy in (score desc, index asc) order — matches stable argsort.
            for (int it = 0; it < V; it++) {
                int   best = -1, bn = 0x7fffffff;
                float bs = -1.0f;
                for (int j = 0; j < V; j++) {
                    if ((used[j >> 5] >> (j & 31)) & 1u) continue;
                    float sj = cs[j];
                    int   nj = cn[j];
                    if (sj > bs || (sj == bs && nj < bn)) { best = j; bs = sj; bn = nj; }
                }
                used[best >> 5] |= 1u << (best & 31);
                if ((sup[best >> 5] >> (best & 31)) & 1u) continue;  // not alive

                float4 bb = cb[best];
                float  ab = (bb.z - bb.x) * (bb.w - bb.y);
                for (int j = 0; j < V; j++) {
                    if ((used[j >> 5] >> (j & 31)) & 1u) continue;
                    if ((sup[j >> 5]  >> (j & 31)) & 1u) continue;
                    float4 cj = cb[j];
                    float iw = fminf(bb.z, cj.z) - fmaxf(bb.x, cj.x);
                    float ih = fminf(bb.w, cj.w) - fmaxf(bb.y, cj.y);
                    iw = fmaxf(iw, 0.0f);
                    ih = fmaxf(ih, 0.0f);
                    float inter = iw * ih;
                    float aj    = (cj.z - cj.x) * (cj.w - cj.y);
                    float uni   = fmaxf(ab + aj - inter, 1e-9f);
                    if (inter / uni > NMS_TH) sup[j >> 5] |= 1u << (j & 31);
                }
            }
            for (int j = 0; j < V; j++) {
                if ((sup[j >> 5] >> (j & 31)) & 1u)
                    out[((size_t)(b * Nn + cn[j])) * CELL + 5 + k] = 0.0f;
            }
        }
    }
}

extern "C" void kernel_launch(void* const* d_in, const int* in_sizes, int n_in,
                              void* d_out, int out_size) {
    const float* x    = (const float*)d_in[0];
    const float* bias = (const float*)d_in[1];
    float* out        = (float*)d_out;
    region_fused<<<NBLK, TPB>>>(x, bias, out);
}

// round 11
// speedup vs baseline: 1.1895x; 1.1895x over previous
#include <cuda_runtime.h>
#include <math.h>

#define Bn 32
#define Rr 13
#define Cc 13
#define Aa 5
#define Kk 20
#define CELL 25
#define Nn 845                        // R*C*A
#define TOTAL (Bn * Nn)               // 27040
#define THRESH 0.5f
#define NMS_TH 0.4f

#define CPB 184                       // cells per block (184*25*4B = 18400B, 16B-aligned)
#define TPB 192
#define NBLK ((TOTAL + CPB - 1) / CPB)    // 147 (last block: 176 cells)
#define NBK (Bn * Kk)                 // 640
#define CAPS 64                       // candidate capacity per (b,k)

// Static device scratch (no allocations allowed).
__device__ float        g_cs[NBK * CAPS];   // candidate scores
__device__ short        g_cn[NBK * CAPS];   // candidate box index n
__device__ float4       g_cb[NBK * CAPS];   // candidate boxes (x1,y1,x2,y2)
__device__ int          g_cnt[NBK];         // per-(b,k) counts (reset by tail)
__device__ unsigned int g_done;             // done-block counter (reset by last block)

__device__ __forceinline__ float sigmoid_(float v) {
    return 1.0f / (1.0f + __expf(-v));
}

__global__ void __launch_bounds__(TPB)
region_fused(const float* __restrict__ x,
             const float* __restrict__ bias,
             float* __restrict__ out) {
    const int tid = threadIdx.x;
    const int blockBase = blockIdx.x * CPB;          // first cell of this block
    const int cells = min(CPB, TOTAL - blockBase);   // 184 or 176
    const int n4 = cells * CELL / 4;                 // 1150 or 1100 (both /4 exact)

    __shared__ float    s_data[CPB * CELL];          // 18.4 KB
    __shared__ unsigned s_done;

    // ---- Coalesced float4 load (blockBase*100B is 16B-aligned: 18400*bid).
    {
        const float4* src = (const float4*)(x + (size_t)blockBase * CELL);
        float4* dst = (float4*)s_data;
        for (int i = tid; i < n4; i += TPB) dst[i] = src[i];
    }
    __syncthreads();

    // ---- Decode + inline softmax, in place in shared.
    if (tid < cells) {
        float* t = s_data + tid * CELL;              // stride 25: conflict-free
        const int gid = blockBase + tid;
        const int n    = gid % Nn;
        const int a    = n % Aa;
        const int cell = n / Aa;
        const int col  = cell % Cc;
        const int row  = cell / Cc;

        float bx  = (sigmoid_(t[0]) + (float)col) * (1.0f / (float)Cc);
        float by  = (sigmoid_(t[1]) + (float)row) * (1.0f / (float)Rr);
        float bw  = __expf(t[2]) * __ldg(&bias[2 * a])     * (1.0f / (float)Rr);
        float bh  = __expf(t[3]) * __ldg(&bias[2 * a + 1]) * (1.0f / (float)Cc);
        float obj = sigmoid_(t[4]);

        t[0] = bx; t[1] = by; t[2] = bw; t[3] = bh; t[4] = obj;

        if (obj > THRESH) {
            float e[Kk];
            float s = 0.0f;
            #pragma unroll
            for (int j = 0; j < Kk; j++) { e[j] = __expf(t[5 + j]); s += e[j]; }
            float inv = 1.0f / s;

            float x1 = bx - 0.5f * bw;
            float y1 = by - 0.5f * bh;
            float4 box = make_float4(x1, y1, x1 + bw, y1 + bh);
            const int b2 = gid / Nn;

            #pragma unroll
            for (int j = 0; j < Kk; j++) {
                float p = obj * e[j] * inv;
                if (p > THRESH) {
                    t[5 + j] = p;
                    int slot = b2 * Kk + j;
                    int q = atomicAdd(&g_cnt[slot], 1);
                    if (q < CAPS) {
                        g_cs[slot * CAPS + q] = p;
                        g_cn[slot * CAPS + q] = (short)n;
                        g_cb[slot * CAPS + q] = box;
                    }
                } else {
                    t[5 + j] = 0.0f;
                }
            }
        } else {
            #pragma unroll
            for (int j = 0; j < Kk; j++) t[5 + j] = 0.0f;
        }
    }
    __syncthreads();

    // ---- Coalesced float4 store.
    {
        const float4* src = (const float4*)s_data;
        float4* dst = (float4*)(out + (size_t)blockBase * CELL);
        for (int i = tid; i < n4; i += TPB) dst[i] = src[i];
    }

    // ---- Done-barrier: last finishing block runs the tiny NMS tail.
    __threadfence();
    __syncthreads();
    if (tid == 0) s_done = atomicAdd(&g_done, 1u);
    __syncthreads();
    if (s_done != (unsigned)(NBLK - 1)) return;

    if (tid == 0) g_done = 0;           // reset for next graph replay
    __threadfence();

    // ---- NMS tail (last block only): greedy per-(b,k) over compacted lists.
    for (int t = tid; t < NBK; t += TPB) {
        int V = g_cnt[t];
        g_cnt[t] = 0;                   // reset for next replay
        if (V > CAPS) V = CAPS;
        if (V <= 1) continue;

        const int b = t / Kk;
        const int k = t % Kk;
        const float*  cs = g_cs + (size_t)t * CAPS;
        const short*  cn = g_cn + (size_t)t * CAPS;
        const float4* cb = g_cb + (size_t)t * CAPS;

        unsigned sup[2] = {0u, 0u}, used[2] = {0u, 0u};

        // Greedy in (score desc, index asc) order — matches stable argsort.
        for (int it = 0; it < V; it++) {
            int   best = -1, bi = 0x7fffffff;
            float bs = -1.0f;
            for (int j = 0; j < V; j++) {
                if ((used[j >> 5] >> (j & 31)) & 1u) continue;
                float sj = cs[j];
                int   nj = cn[j];
                if (sj > bs || (sj == bs && nj < bi)) { best = j; bs = sj; bi = nj; }
            }
            used[best >> 5] |= 1u << (best & 31);
            if ((sup[best >> 5] >> (best & 31)) & 1u) continue;   // not alive

            float4 bb = cb[best];
            float  ab = (bb.z - bb.x) * (bb.w - bb.y);
            for (int j = 0; j < V; j++) {
                if ((used[j >> 5] >> (j & 31)) & 1u) continue;
                if ((sup[j >> 5]  >> (j & 31)) & 1u) continue;
                float4 cj = cb[j];
                float iw = fminf(bb.z, cj.z) - fmaxf(bb.x, cj.x);
                float ih = fminf(bb.w, cj.w) - fmaxf(bb.y, cj.y);
                iw = fmaxf(iw, 0.0f);
                ih = fmaxf(ih, 0.0f);
                float inter = iw * ih;
                float aj    = (cj.z - cj.x) * (cj.w - cj.y);
                float uni   = fmaxf(ab + aj - inter, 1e-9f);
                if (inter / uni > NMS_TH) sup[j >> 5] |= 1u << (j & 31);
            }
        }
        for (int j = 0; j < V; j++) {
            if ((sup[j >> 5] >> (j & 31)) & 1u)
                out[((size_t)(b * Nn + cn[j])) * CELL + 5 + k] = 0.0f;
        }
    }
}

extern "C" void kernel_launch(void* const* d_in, const int* in_sizes, int n_in,
                              void* d_out, int out_size) {
    const float* x    = (const float*)d_in[0];
    const float* bias = (const float*)d_in[1];
    float* out        = (float*)d_out;
    region_fused<<<NBLK, TPB>>>(x, bias, out);
}

// round 12
// speedup vs baseline: 1.2143x; 1.0208x over previous
#include <cuda_runtime.h>
#include <math.h>

#define Bn 32
#define Rr 13
#define Cc 13
#define Aa 5
#define Kk 20
#define CELL 25
#define Nn 845                        // R*C*A
#define TOTAL (Bn * Nn)               // 27040
#define THRESH 0.5f
#define NMS_TH 0.4f

#define CPB 128                       // cells/block: 128*100B = 12800B, 16B-aligned
#define TPB 128
#define NBLK ((TOTAL + CPB - 1) / CPB)    // 212 (last block: 32 cells)
#define NBK (Bn * Kk)                 // 640
#define CAPS 64                       // candidate capacity per (b,k)

// Static device scratch (no allocations allowed).
__device__ float                 g_cs[NBK * CAPS];
__device__ short                 g_cn[NBK * CAPS];
__device__ float4                g_cb[NBK * CAPS];
__device__ __align__(16) int     g_cnt[NBK];      // reset by tail each replay
__device__ unsigned int          g_done;          // reset by last block

__device__ __forceinline__ float sigmoid_(float v) {
    return 1.0f / (1.0f + __expf(-v));
}

__global__ void __launch_bounds__(TPB)
region_fused(const float* __restrict__ x,
             const float* __restrict__ bias,
             float* __restrict__ out) {
    const int tid = threadIdx.x;
    const int blockBase = blockIdx.x * CPB;
    const int cells = min(CPB, TOTAL - blockBase);   // 128 or 32
    const int n4 = cells * CELL / 4;                 // 800 or 200

    __shared__ float    s_data[CPB * CELL];          // 12.8 KB
    __shared__ int      s_slots[NBK];                // tail: packed slot|V<<16
    __shared__ int      s_m;
    __shared__ unsigned s_done;

    // ---- Hoist per-cell index math + bias loads (overlap with staging loads).
    const int  gid   = blockBase + tid;
    const bool valid = (tid < cells);
    int n = 0, col = 0, row = 0, b2 = 0;
    float wb = 0.0f, hb = 0.0f;
    if (valid) {
        n = gid % Nn;
        b2 = gid / Nn;
        int a    = n % Aa;
        int cell = n / Aa;
        col = cell % Cc;
        row = cell / Cc;
        wb = __ldg(&bias[2 * a]);
        hb = __ldg(&bias[2 * a + 1]);
    }

    // ---- Coalesced float4 staging load.
    {
        const float4* src = (const float4*)(x + (size_t)blockBase * CELL);
        float4* dst = (float4*)s_data;
        for (int i = tid; i < n4; i += TPB) dst[i] = src[i];
    }
    __syncthreads();

    // ---- Decode + inline softmax, in place in shared.
    if (valid) {
        float* t = s_data + tid * CELL;              // stride 25: conflict-free

        float bx  = (sigmoid_(t[0]) + (float)col) * (1.0f / (float)Cc);
        float by  = (sigmoid_(t[1]) + (float)row) * (1.0f / (float)Rr);
        float bw  = __expf(t[2]) * wb * (1.0f / (float)Rr);
        float bh  = __expf(t[3]) * hb * (1.0f / (float)Cc);
        float obj = sigmoid_(t[4]);

        t[0] = bx; t[1] = by; t[2] = bw; t[3] = bh; t[4] = obj;

        if (obj > THRESH) {
            float e[Kk];
            float s = 0.0f;
            #pragma unroll
            for (int j = 0; j < Kk; j++) { e[j] = __expf(t[5 + j]); s += e[j]; }
            float inv = 1.0f / s;

            float x1 = bx - 0.5f * bw;
            float y1 = by - 0.5f * bh;
            float4 box = make_float4(x1, y1, x1 + bw, y1 + bh);

            #pragma unroll
            for (int j = 0; j < Kk; j++) {
                float p = obj * e[j] * inv;
                if (p > THRESH) {
                    t[5 + j] = p;
                    int slot = b2 * Kk + j;
                    int q = atomicAdd(&g_cnt[slot], 1);
                    if (q < CAPS) {
                        g_cs[slot * CAPS + q] = p;
                        g_cn[slot * CAPS + q] = (short)n;
                        g_cb[slot * CAPS + q] = box;
                    }
                } else {
                    t[5 + j] = 0.0f;
                }
            }
        } else {
            #pragma unroll
            for (int j = 0; j < Kk; j++) t[5 + j] = 0.0f;
        }
    }
    __syncthreads();

    // ---- Coalesced float4 store.
    {
        const float4* src = (const float4*)s_data;
        float4* dst = (float4*)(out + (size_t)blockBase * CELL);
        for (int i = tid; i < n4; i += TPB) dst[i] = src[i];
    }

    // ---- Done-barrier: last finishing block runs the NMS tail.
    __threadfence();
    __syncthreads();
    if (tid == 0) s_done = atomicAdd(&g_done, 1u);
    __syncthreads();
    if (s_done != (unsigned)(NBLK - 1)) return;

    if (tid == 0) { g_done = 0; s_m = 0; }        // resets for next replay
    __syncthreads();

    // ---- Tail step 1: vectorized g_cnt read+reset, compact V>=2 slots.
    {
        int4* cnt4 = (int4*)g_cnt;
        for (int i = tid; i < NBK / 4; i += TPB) {
            int4 v = cnt4[i];
            cnt4[i] = make_int4(0, 0, 0, 0);
            int base = i * 4;
            if (v.x > 1) s_slots[atomicAdd(&s_m, 1)] = base     | (min(v.x, CAPS) << 16);
            if (v.y > 1) s_slots[atomicAdd(&s_m, 1)] = (base+1) | (min(v.y, CAPS) << 16);
            if (v.z > 1) s_slots[atomicAdd(&s_m, 1)] = (base+2) | (min(v.z, CAPS) << 16);
            if (v.w > 1) s_slots[atomicAdd(&s_m, 1)] = (base+3) | (min(v.w, CAPS) << 16);
        }
    }
    __syncthreads();

    // ---- Tail step 2: greedy NMS per compacted slot.
    const int m = s_m;
    for (int ii = tid; ii < m; ii += TPB) {
        const int packed = s_slots[ii];
        const int t = packed & 0xFFFF;
        const int V = packed >> 16;
        const int b = t / Kk;
        const int k = t % Kk;
        const float*  cs = g_cs + (size_t)t * CAPS;
        const short*  cn = g_cn + (size_t)t * CAPS;
        const float4* cb = g_cb + (size_t)t * CAPS;

        unsigned sup[2] = {0u, 0u}, used[2] = {0u, 0u};

        // Greedy in (score desc, index asc) order — matches stable argsort.
        for (int it = 0; it < V; it++) {
            int   best = -1, bi = 0x7fffffff;
            float bs = -1.0f;
            for (int j = 0; j < V; j++) {
                if ((used[j >> 5] >> (j & 31)) & 1u) continue;
                float sj = cs[j];
                int   nj = cn[j];
                if (sj > bs || (sj == bs && nj < bi)) { best = j; bs = sj; bi = nj; }
            }
            used[best >> 5] |= 1u << (best & 31);
            if ((sup[best >> 5] >> (best & 31)) & 1u) continue;   // not alive

            float4 bb = cb[best];
            float  ab = (bb.z - bb.x) * (bb.w - bb.y);
            for (int j = 0; j < V; j++) {
                if ((used[j >> 5] >> (j & 31)) & 1u) continue;
                if ((sup[j >> 5]  >> (j & 31)) & 1u) continue;
                float4 cj = cb[j];
                float iw = fminf(bb.z, cj.z) - fmaxf(bb.x, cj.x);
                float ih = fminf(bb.w, cj.w) - fmaxf(bb.y, cj.y);
                iw = fmaxf(iw, 0.0f);
                ih = fmaxf(ih, 0.0f);
                float inter = iw * ih;
                float aj    = (cj.z - cj.x) * (cj.w - cj.y);
                float uni   = fmaxf(ab + aj - inter, 1e-9f);
                if (inter / uni > NMS_TH) sup[j >> 5] |= 1u << (j & 31);
            }
        }
        for (int j = 0; j < V; j++) {
            if ((sup[j >> 5] >> (j & 31)) & 1u)
                out[((size_t)(b * Nn + cn[j])) * CELL + 5 + k] = 0.0f;
        }
    }
}

extern "C" void kernel_launch(void* const* d_in, const int* in_sizes, int n_in,
                              void* d_out, int out_size) {
    const float* x    = (const float*)d_in[0];
    const float* bias = (const float*)d_in[1];
    float* out        = (float*)d_out;
    region_fused<<<NBLK, TPB>>>(x, bias, out);
}

// round 13
// speedup vs baseline: 1.5055x; 1.2399x over previous
#include <cuda_runtime.h>
#include <math.h>

#define Bn 32
#define Rr 13
#define Cc 13
#define Aa 5
#define Kk 20
#define CELL 25
#define Nn 845                        // R*C*A
#define TOTAL (Bn * Nn)               // 27040
#define THRESH 0.5f
#define NMS_TH 0.4f

#define CPB 128                       // cells/block: 128*100B = 12800B, 16B-aligned
#define TPB 128
#define NBLK ((TOTAL + CPB - 1) / CPB)    // 212 (last block: 32 cells)
#define NBK (Bn * Kk)                 // 640
#define CAPS 64                       // candidate capacity per (b,k)

// Static device scratch (no allocations allowed).
__device__ float                 g_cs[NBK * CAPS];
__device__ short                 g_cn[NBK * CAPS];
__device__ float4                g_cb[NBK * CAPS];
__device__ __align__(16) int     g_cnt[NBK];      // reset by NMS kernel each replay

__device__ __forceinline__ float sigmoid_(float v) {
    return 1.0f / (1.0f + __expf(-v));
}

// ---------------- Kernel A: decode + softmax + candidate compaction ----------
__global__ void __launch_bounds__(TPB)
region_decode(const float* __restrict__ x,
              const float* __restrict__ bias,
              float* __restrict__ out) {
    const int tid = threadIdx.x;
    const int blockBase = blockIdx.x * CPB;
    const int cells = min(CPB, TOTAL - blockBase);   // 128 or 32
    const int n4 = cells * CELL / 4;                 // 800 or 200

    __shared__ float s_data[CPB * CELL];             // 12.8 KB

    // Hoist per-cell index math + bias loads (overlap with staging loads).
    const int  gid   = blockBase + tid;
    const bool valid = (tid < cells);
    int n = 0, col = 0, row = 0, b2 = 0;
    float wb = 0.0f, hb = 0.0f;
    if (valid) {
        n  = gid % Nn;
        b2 = gid / Nn;
        int a    = n % Aa;
        int cell = n / Aa;
        col = cell % Cc;
        row = cell / Cc;
        wb = __ldg(&bias[2 * a]);
        hb = __ldg(&bias[2 * a + 1]);
    }

    // Coalesced float4 staging load.
    {
        const float4* src = (const float4*)(x + (size_t)blockBase * CELL);
        float4* dst = (float4*)s_data;
        for (int i = tid; i < n4; i += TPB) dst[i] = src[i];
    }
    __syncthreads();

    // Decode + inline softmax, in place in shared.
    if (valid) {
        float* t = s_data + tid * CELL;              // stride 25: conflict-free

        float bx  = (sigmoid_(t[0]) + (float)col) * (1.0f / (float)Cc);
        float by  = (sigmoid_(t[1]) + (float)row) * (1.0f / (float)Rr);
        float bw  = __expf(t[2]) * wb * (1.0f / (float)Rr);
        float bh  = __expf(t[3]) * hb * (1.0f / (float)Cc);
        float obj = sigmoid_(t[4]);

        t[0] = bx; t[1] = by; t[2] = bw; t[3] = bh; t[4] = obj;

        if (obj > THRESH) {
            float e[Kk];
            float s = 0.0f;
            #pragma unroll
            for (int j = 0; j < Kk; j++) { e[j] = __expf(t[5 + j]); s += e[j]; }
            float inv = 1.0f / s;

            float x1 = bx - 0.5f * bw;
            float y1 = by - 0.5f * bh;
            float4 box = make_float4(x1, y1, x1 + bw, y1 + bh);

            #pragma unroll
            for (int j = 0; j < Kk; j++) {
                float p = obj * e[j] * inv;
                if (p > THRESH) {
                    t[5 + j] = p;
                    int slot = b2 * Kk + j;
                    int q = atomicAdd(&g_cnt[slot], 1);
                    if (q < CAPS) {
                        g_cs[slot * CAPS + q] = p;
                        g_cn[slot * CAPS + q] = (short)n;
                        g_cb[slot * CAPS + q] = box;
                    }
                } else {
                    t[5 + j] = 0.0f;
                }
            }
        } else {
            #pragma unroll
            for (int j = 0; j < Kk; j++) t[5 + j] = 0.0f;
        }
    }
    __syncthreads();

    // Coalesced float4 store.
    {
        const float4* src = (const float4*)s_data;
        float4* dst = (float4*)(out + (size_t)blockBase * CELL);
        for (int i = tid; i < n4; i += TPB) dst[i] = src[i];
    }
}

// ---------------- Kernel B: tiny NMS over compacted candidate lists ----------
__global__ void __launch_bounds__(TPB)
region_nms(float* __restrict__ out) {
    const int tid = threadIdx.x;

    __shared__ int s_slots[NBK];      // packed slot | V<<16
    __shared__ int s_m;

    if (tid == 0) s_m = 0;
    __syncthreads();

    // Vectorized g_cnt read + reset; compact V>=2 slots.
    {
        int4* cnt4 = (int4*)g_cnt;
        for (int i = tid; i < NBK / 4; i += TPB) {
            int4 v = cnt4[i];
            cnt4[i] = make_int4(0, 0, 0, 0);
            int base = i * 4;
            if (v.x > 1) s_slots[atomicAdd(&s_m, 1)] = base     | (min(v.x, CAPS) << 16);
            if (v.y > 1) s_slots[atomicAdd(&s_m, 1)] = (base+1) | (min(v.y, CAPS) << 16);
            if (v.z > 1) s_slots[atomicAdd(&s_m, 1)] = (base+2) | (min(v.z, CAPS) << 16);
            if (v.w > 1) s_slots[atomicAdd(&s_m, 1)] = (base+3) | (min(v.w, CAPS) << 16);
        }
    }
    __syncthreads();

    const int m = s_m;
    for (int ii = tid; ii < m; ii += TPB) {
        const int packed = s_slots[ii];
        const int t = packed & 0xFFFF;
        const int V = packed >> 16;
        const int b = t / Kk;
        const int k = t % Kk;
        const float*  cs = g_cs + (size_t)t * CAPS;
        const short*  cn = g_cn + (size_t)t * CAPS;
        const float4* cb = g_cb + (size_t)t * CAPS;

        unsigned sup[2] = {0u, 0u}, used[2] = {0u, 0u};

        // Greedy in (score desc, index asc) order — matches stable argsort.
        for (int it = 0; it < V; it++) {
            int   best = -1, bi = 0x7fffffff;
            float bs = -1.0f;
            for (int j = 0; j < V; j++) {
                if ((used[j >> 5] >> (j & 31)) & 1u) continue;
                float sj = cs[j];
                int   nj = cn[j];
                if (sj > bs || (sj == bs && nj < bi)) { best = j; bs = sj; bi = nj; }
            }
            used[best >> 5] |= 1u << (best & 31);
            if ((sup[best >> 5] >> (best & 31)) & 1u) continue;   // not alive

            float4 bb = cb[best];
            float  ab = (bb.z - bb.x) * (bb.w - bb.y);
            for (int j = 0; j < V; j++) {
                if ((used[j >> 5] >> (j & 31)) & 1u) continue;
                if ((sup[j >> 5]  >> (j & 31)) & 1u) continue;
                float4 cj = cb[j];
                float iw = fminf(bb.z, cj.z) - fmaxf(bb.x, cj.x);
                float ih = fminf(bb.w, cj.w) - fmaxf(bb.y, cj.y);
                iw = fmaxf(iw, 0.0f);
                ih = fmaxf(ih, 0.0f);
                float inter = iw * ih;
                float aj    = (cj.z - cj.x) * (cj.w - cj.y);
                float uni   = fmaxf(ab + aj - inter, 1e-9f);
                if (inter / uni > NMS_TH) sup[j >> 5] |= 1u << (j & 31);
            }
        }
        for (int j = 0; j < V; j++) {
            if ((sup[j >> 5] >> (j & 31)) & 1u)
                out[((size_t)(b * Nn + cn[j])) * CELL + 5 + k] = 0.0f;
        }
    }
}

extern "C" void kernel_launch(void* const* d_in, const int* in_sizes, int n_in,
                              void* d_out, int out_size) {
    const float* x    = (const float*)d_in[0];
    const float* bias = (const float*)d_in[1];
    float* out        = (float*)d_out;
    region_decode<<<NBLK, TPB>>>(x, bias, out);
    region_nms<<<1, TPB>>>(out);
}